// round 1
// baseline (speedup 1.0000x reference)
#include <cuda_runtime.h>
#include <math.h>

#define Bb 512
#define Ff 64
#define Tt 64
#define Hh 512
#define Kk 4

// ---------------- scratch (static device globals; no allocation) ----------------
__device__ float g_dataT[(size_t)Tt * Bb * Ff];          // [t][b][f]
__device__ float g_xseq[(size_t)Kk * Tt * Bb * Hh];      // [k][t][b][h]  (sequence order per cell)
__device__ float g_gi[(size_t)Kk * Tt * Bb * 3 * Hh];    // [k][t][b][3H]
__device__ float g_gh[(size_t)Kk * Bb * 3 * Hh];         // [k][b][3H]
__device__ float g_h[(size_t)Kk * Bb * Hh];              // [k][b][h]
__device__ float g_hs[(size_t)Kk * Tt * Bb * Hh];        // [k][t][b][h]

// ---------------- data transpose: [B,F,T] -> [T,B,F] ----------------
__global__ void transpose_data(const float* __restrict__ data) {
    int idx = blockIdx.x * blockDim.x + threadIdx.x;
    if (idx >= Tt * Bb * Ff) return;
    int f = idx % Ff;
    int b = (idx / Ff) % Bb;
    int t = idx / (Ff * Bb);
    g_dataT[idx] = data[(size_t)b * Ff * Tt + (size_t)f * Tt + t];
}

// ---------------- input projection + ReLU -> xseq ----------------
// xseq[k][t][b][h] = relu( sum_f dataT[tt][b][f] * fcW[k][h][f] + fcB[k][h] )
// tt = t for k<2, T-1-t for k>=2 (backward cells consume reversed sequence)
__global__ void __launch_bounds__(256) proj_kernel(const float* __restrict__ fcW,
                                                   const float* __restrict__ fcB) {
    int kt = blockIdx.z;
    int k = kt >> 6;
    int t = kt & 63;
    int tt = (k < 2) ? t : (Tt - 1 - t);
    const float* A  = g_dataT + (size_t)tt * Bb * Ff;      // [B][F]
    const float* Wk = fcW + (size_t)k * Hh * Ff;           // [H][F]
    int b0 = blockIdx.x * 64, h0 = blockIdx.y * 64;

    __shared__ float As[Ff][64];   // [f][b]
    __shared__ float Ws[Ff][64];   // [f][h]
    int tid = threadIdx.x;

#pragma unroll
    for (int i = 0; i < 4; i++) {
        int li = tid + i * 256;          // float4 index, 0..1023
        int row = li >> 4;               // 16 float4 per 64-float row
        int fq = (li & 15) << 2;
        float4 v = *(const float4*)(A + (size_t)(b0 + row) * Ff + fq);
        As[fq + 0][row] = v.x; As[fq + 1][row] = v.y;
        As[fq + 2][row] = v.z; As[fq + 3][row] = v.w;
        float4 w = *(const float4*)(Wk + (size_t)(h0 + row) * Ff + fq);
        Ws[fq + 0][row] = w.x; Ws[fq + 1][row] = w.y;
        Ws[fq + 2][row] = w.z; Ws[fq + 3][row] = w.w;
    }
    __syncthreads();

    int ty = tid >> 4, tx = tid & 15;
    float acc[4][4] = {};
#pragma unroll 8
    for (int f = 0; f < Ff; f++) {
        float4 a = *(const float4*)&As[f][ty * 4];
        float4 w = *(const float4*)&Ws[f][tx * 4];
        float av[4] = {a.x, a.y, a.z, a.w};
        float wv[4] = {w.x, w.y, w.z, w.w};
#pragma unroll
        for (int i = 0; i < 4; i++)
#pragma unroll
            for (int j = 0; j < 4; j++) acc[i][j] += av[i] * wv[j];
    }

#pragma unroll
    for (int i = 0; i < 4; i++) {
        int b = b0 + ty * 4 + i;
        int h = h0 + tx * 4;
        float4 o;
        o.x = fmaxf(acc[i][0] + fcB[k * Hh + h + 0], 0.f);
        o.y = fmaxf(acc[i][1] + fcB[k * Hh + h + 1], 0.f);
        o.z = fmaxf(acc[i][2] + fcB[k * Hh + h + 2], 0.f);
        o.w = fmaxf(acc[i][3] + fcB[k * Hh + h + 3], 0.f);
        *(float4*)(g_xseq + ((((size_t)k * Tt + t) * Bb + b) * Hh) + h) = o;
    }
}

// ---------------- generic NT SGEMM + bias ----------------
// C[m][n] = sum_i A[m][i] * W[n][i] + bias[n]
// MODE 0: A = g_xseq (+z*sA), C = g_gi (+z*sC)    (gi precompute, M = T*B)
// MODE 1: A = g_h    (+z*sA), C = g_gh (+z*sC)    (per-step gh, M = B)
template <int MODE>
__global__ void __launch_bounds__(256) sgemm_nt_bias(
    const float* __restrict__ Wb, const float* __restrict__ biasb,
    int M, int Kd, int N,
    long long sA, long long sW, long long sB, long long sC)
{
    const float* A = (MODE == 0 ? g_xseq : g_h) + (size_t)blockIdx.z * sA;
    float* C       = (MODE == 0 ? g_gi   : g_gh) + (size_t)blockIdx.z * sC;
    const float* W = Wb + (size_t)blockIdx.z * sW;
    const float* bias = biasb + (size_t)blockIdx.z * sB;

    int m0 = blockIdx.x * 128, n0 = blockIdx.y * 128;
    __shared__ float As[16][128];
    __shared__ float Bs[16][128];
    int tid = threadIdx.x;
    int ty = tid >> 4, tx = tid & 15;
    float acc[8][8] = {};

    for (int k0 = 0; k0 < Kd; k0 += 16) {
#pragma unroll
        for (int i = 0; i < 2; i++) {
            int li = tid + i * 256;        // float4 index, 0..511
            int row = li >> 2;             // 4 float4 per 16-float slab row
            int kq = (li & 3) << 2;
            float4 v = *(const float4*)(A + (size_t)(m0 + row) * Kd + k0 + kq);
            As[kq + 0][row] = v.x; As[kq + 1][row] = v.y;
            As[kq + 2][row] = v.z; As[kq + 3][row] = v.w;
            float4 w = *(const float4*)(W + (size_t)(n0 + row) * Kd + k0 + kq);
            Bs[kq + 0][row] = w.x; Bs[kq + 1][row] = w.y;
            Bs[kq + 2][row] = w.z; Bs[kq + 3][row] = w.w;
        }
        __syncthreads();
#pragma unroll
        for (int kk = 0; kk < 16; kk++) {
            float a[8], b[8];
            *(float4*)&a[0] = *(const float4*)&As[kk][ty * 4];
            *(float4*)&a[4] = *(const float4*)&As[kk][64 + ty * 4];
            *(float4*)&b[0] = *(const float4*)&Bs[kk][tx * 4];
            *(float4*)&b[4] = *(const float4*)&Bs[kk][64 + tx * 4];
#pragma unroll
            for (int i = 0; i < 8; i++)
#pragma unroll
                for (int j = 0; j < 8; j++) acc[i][j] += a[i] * b[j];
        }
        __syncthreads();
    }

#pragma unroll
    for (int ig = 0; ig < 2; ig++)
#pragma unroll
        for (int i = 0; i < 4; i++) {
            int m = m0 + ig * 64 + ty * 4 + i;
#pragma unroll
            for (int jg = 0; jg < 2; jg++) {
                int n = n0 + jg * 64 + tx * 4;
                float4 o;
                o.x = acc[ig * 4 + i][jg * 4 + 0] + bias[n + 0];
                o.y = acc[ig * 4 + i][jg * 4 + 1] + bias[n + 1];
                o.z = acc[ig * 4 + i][jg * 4 + 2] + bias[n + 2];
                o.w = acc[ig * 4 + i][jg * 4 + 3] + bias[n + 3];
                *(float4*)(C + (size_t)m * N + n) = o;
            }
        }
}

// ---------------- h init ----------------
__global__ void init_h_kernel(const float* __restrict__ init) {
    int idx = blockIdx.x * 256 + threadIdx.x;   // K*B*H
    g_h[idx] = init[idx % (Bb * Hh)];
}

// ---------------- GRU gate update (per step) ----------------
__global__ void gru_gates(int t) {
    int idx = blockIdx.x * 256 + threadIdx.x;   // over K*B*H
    int k = idx / (Bb * Hh);
    int rem = idx - k * (Bb * Hh);
    int b = rem / Hh;
    int hh = rem - b * Hh;
    const float* gik = g_gi + (((size_t)k * Tt + t) * Bb + b) * 3 * Hh;
    const float* ghk = g_gh + ((size_t)k * Bb + b) * 3 * Hh;
    float r = 1.f / (1.f + expf(-(gik[hh] + ghk[hh])));
    float z = 1.f / (1.f + expf(-(gik[Hh + hh] + ghk[Hh + hh])));
    float n = tanhf(gik[2 * Hh + hh] + r * ghk[2 * Hh + hh]);
    float hp = g_h[idx];
    float hnew = (1.f - z) * n + z * hp;
    g_h[idx] = hnew;
    g_hs[(((size_t)k * Tt + t) * Bb + b) * Hh + hh] = hnew;
}

// ---------------- output heads ----------------
// out[pair][b][t] = sum_h (hs[pair][t][b][h] + hs[pair+2][T-1-t][b][h]) * Wout[pair][h] + bout[pair]
__global__ void out_kernel(const float* __restrict__ Wout,
                           const float* __restrict__ bout,
                           float* __restrict__ out) {
    int warp = threadIdx.x >> 5;
    int lane = threadIdx.x & 31;
    int oid = blockIdx.x * 8 + warp;   // 0 .. 2*B*T-1
    int pair = oid >> 15;              // B*T = 32768
    int rem = oid & 32767;
    int b = rem >> 6;
    int t = rem & 63;
    const float* hf = g_hs + (((size_t)pair * Tt + t) * Bb + b) * Hh;
    const float* hb = g_hs + (((size_t)(pair + 2) * Tt + (Tt - 1 - t)) * Bb + b) * Hh;
    const float* w = Wout + pair * Hh;
    float s = 0.f;
    for (int i0 = lane * 4; i0 < Hh; i0 += 128) {
        float4 f = *(const float4*)(hf + i0);
        float4 g = *(const float4*)(hb + i0);
        float4 wv = *(const float4*)(w + i0);
        s += (f.x + g.x) * wv.x + (f.y + g.y) * wv.y +
             (f.z + g.z) * wv.z + (f.w + g.w) * wv.w;
    }
#pragma unroll
    for (int o = 16; o; o >>= 1) s += __shfl_xor_sync(0xffffffffu, s, o);
    if (lane == 0) out[(size_t)pair * Bb * Tt + b * Tt + t] = s + bout[pair];
}

// ---------------- launch ----------------
extern "C" void kernel_launch(void* const* d_in, const int* in_sizes, int n_in,
                              void* d_out, int out_size) {
    const float* data     = (const float*)d_in[0];
    const float* init     = (const float*)d_in[1];
    const float* fc_in_W  = (const float*)d_in[2];
    const float* fc_in_b  = (const float*)d_in[3];
    const float* Wih      = (const float*)d_in[4];
    const float* Whh      = (const float*)d_in[5];
    const float* bih      = (const float*)d_in[6];
    const float* bhh      = (const float*)d_in[7];
    const float* fc_out_W = (const float*)d_in[8];
    const float* fc_out_b = (const float*)d_in[9];
    float* out = (float*)d_out;

    transpose_data<<<(Tt * Bb * Ff) / 256, 256>>>(data);
    proj_kernel<<<dim3(Bb / 64, Hh / 64, Kk * Tt), 256>>>(fc_in_W, fc_in_b);

    // gi = xseq @ Wih^T + bih  : M = T*B = 32768, Kd = H, N = 3H, batched over K cells
    sgemm_nt_bias<0><<<dim3((Tt * Bb) / 128, (3 * Hh) / 128, Kk), 256>>>(
        Wih, bih, Tt * Bb, Hh, 3 * Hh,
        (long long)Tt * Bb * Hh, (long long)3 * Hh * Hh, 3 * Hh,
        (long long)Tt * Bb * 3 * Hh);

    init_h_kernel<<<(Kk * Bb * Hh) / 256, 256>>>(init);

    for (int t = 0; t < Tt; t++) {
        // gh = h @ Whh^T + bhh : M = B = 512
        sgemm_nt_bias<1><<<dim3(Bb / 128, (3 * Hh) / 128, Kk), 256>>>(
            Whh, bhh, Bb, Hh, 3 * Hh,
            (long long)Bb * Hh, (long long)3 * Hh * Hh, 3 * Hh,
            (long long)Bb * 3 * Hh);
        gru_gates<<<(Kk * Bb * Hh) / 256, 256>>>(t);
    }

    out_kernel<<<(2 * Bb * Tt) / 8, 256>>>(fc_out_W, fc_out_b, out);
}

// round 5
// speedup vs baseline: 2.4004x; 2.4004x over previous
#include <cuda_runtime.h>
#include <cuda_bf16.h>
#include <math.h>
#include <stdint.h>

#define Bb 512
#define Ff 64
#define Tt 64
#define Hh 512
#define Kk 4
#define NN (3 * Hh)   // 1536

// ---------------- scratch (static device globals; no allocation) ----------------
__device__ __align__(16) float g_dataT[(size_t)Tt * Bb * Ff];            // [t][b][f]
__device__ __align__(16) __nv_bfloat16 g_xh[(size_t)Kk * Tt * Bb * Hh];  // x split hi
__device__ __align__(16) __nv_bfloat16 g_xl[(size_t)Kk * Tt * Bb * Hh];  // x split lo
__device__ __align__(16) __nv_bfloat16 g_Wih_h[(size_t)Kk * NN * Hh];
__device__ __align__(16) __nv_bfloat16 g_Wih_l[(size_t)Kk * NN * Hh];
__device__ __align__(16) __nv_bfloat16 g_Whh_h[(size_t)Kk * NN * Hh];
__device__ __align__(16) __nv_bfloat16 g_Whh_l[(size_t)Kk * NN * Hh];
__device__ __align__(16) __nv_bfloat16 g_hh[(size_t)Kk * Bb * Hh];
__device__ __align__(16) __nv_bfloat16 g_hl[(size_t)Kk * Bb * Hh];
__device__ __align__(16) float g_gi[(size_t)Kk * Tt * Bb * NN];          // [k][(t,b)][3H]
__device__ __align__(16) float g_gh[(size_t)Kk * Bb * NN];               // [k][b][3H]
__device__ __align__(16) float g_h[(size_t)Kk * Bb * Hh];                // [k][b][h]
__device__ __align__(16) float g_hs[(size_t)Kk * Tt * Bb * Hh];          // [k][t][b][h]

// ---------------- helpers ----------------
__device__ __forceinline__ uint32_t smem_u32(const void* p) {
    uint32_t a;
    asm("{ .reg .u64 t; cvta.to.shared.u64 t, %1; cvt.u32.u64 %0, t; }" : "=r"(a) : "l"(p));
    return a;
}
__device__ __forceinline__ void cp16(uint32_t saddr, const void* g) {
    asm volatile("cp.async.cg.shared.global [%0], [%1], 16;" :: "r"(saddr), "l"(g));
}
__device__ __forceinline__ void cp_commit() {
    asm volatile("cp.async.commit_group;" ::: "memory");
}
template <int N> __device__ __forceinline__ void cp_wait() {
    asm volatile("cp.async.wait_group %0;" :: "n"(N) : "memory");
}
__device__ __forceinline__ void ldsm_x4(uint32_t a, uint32_t* r) {
    asm volatile("ldmatrix.sync.aligned.m8n8.x4.shared.b16 {%0,%1,%2,%3}, [%4];"
                 : "=r"(r[0]), "=r"(r[1]), "=r"(r[2]), "=r"(r[3]) : "r"(a));
}
__device__ __forceinline__ void mma16816(float* d, const uint32_t* a, const uint32_t* b) {
    asm volatile(
        "mma.sync.aligned.m16n8k16.row.col.f32.bf16.bf16.f32 "
        "{%0,%1,%2,%3}, {%4,%5,%6,%7}, {%8,%9}, {%0,%1,%2,%3};"
        : "+f"(d[0]), "+f"(d[1]), "+f"(d[2]), "+f"(d[3])
        : "r"(a[0]), "r"(a[1]), "r"(a[2]), "r"(a[3]), "r"(b[0]), "r"(b[1]));
}

// swizzle for 64B rows: chunk (0..3) ^= (row>>1)&3
__device__ __forceinline__ uint32_t swz64(int r, int c) {
    return (uint32_t)(r * 64 + ((c ^ ((r >> 1) & 3)) << 4));
}

// ---------------- data transpose: [B,F,T] -> [T,B,F] ----------------
__global__ void transpose_data(const float* __restrict__ data) {
    int idx = blockIdx.x * blockDim.x + threadIdx.x;
    if (idx >= Tt * Bb * Ff) return;
    int f = idx % Ff;
    int b = (idx / Ff) % Bb;
    int t = idx / (Ff * Bb);
    g_dataT[idx] = data[(size_t)b * Ff * Tt + (size_t)f * Tt + t];
}

// ---------------- input projection + ReLU -> x splits ----------------
__global__ void __launch_bounds__(256) proj_kernel(const float* __restrict__ fcW,
                                                   const float* __restrict__ fcB) {
    int kt = blockIdx.z;
    int k = kt >> 6;
    int t = kt & 63;
    int tt = (k < 2) ? t : (Tt - 1 - t);
    const float* A  = g_dataT + (size_t)tt * Bb * Ff;
    const float* Wk = fcW + (size_t)k * Hh * Ff;
    int b0 = blockIdx.x * 64, h0 = blockIdx.y * 64;

    __shared__ float As[Ff][64];
    __shared__ float Ws[Ff][64];
    int tid = threadIdx.x;

#pragma unroll
    for (int i = 0; i < 4; i++) {
        int li = tid + i * 256;
        int row = li >> 4;
        int fq = (li & 15) << 2;
        float4 v = *(const float4*)(A + (size_t)(b0 + row) * Ff + fq);
        As[fq + 0][row] = v.x; As[fq + 1][row] = v.y;
        As[fq + 2][row] = v.z; As[fq + 3][row] = v.w;
        float4 w = *(const float4*)(Wk + (size_t)(h0 + row) * Ff + fq);
        Ws[fq + 0][row] = w.x; Ws[fq + 1][row] = w.y;
        Ws[fq + 2][row] = w.z; Ws[fq + 3][row] = w.w;
    }
    __syncthreads();

    int ty = tid >> 4, tx = tid & 15;
    float acc[4][4] = {};
#pragma unroll 8
    for (int f = 0; f < Ff; f++) {
        float4 a = *(const float4*)&As[f][ty * 4];
        float4 w = *(const float4*)&Ws[f][tx * 4];
        float av[4] = {a.x, a.y, a.z, a.w};
        float wv[4] = {w.x, w.y, w.z, w.w};
#pragma unroll
        for (int i = 0; i < 4; i++)
#pragma unroll
            for (int j = 0; j < 4; j++) acc[i][j] += av[i] * wv[j];
    }

#pragma unroll
    for (int i = 0; i < 4; i++) {
        int b = b0 + ty * 4 + i;
        size_t rowoff = (((size_t)k * Tt + t) * Bb + b) * Hh;
#pragma unroll
        for (int j = 0; j < 4; j++) {
            int h = h0 + tx * 4 + j;
            float v = fmaxf(acc[i][j] + fcB[k * Hh + h], 0.f);
            __nv_bfloat16 hi = __float2bfloat16(v);
            g_xh[rowoff + h] = hi;
            g_xl[rowoff + h] = __float2bfloat16(v - __bfloat162float(hi));
        }
    }
}

// ---------------- weight splitting ----------------
__global__ void split_w(const float* __restrict__ Wih, const float* __restrict__ Whh) {
    const int NW = Kk * NN * Hh;
    int idx = blockIdx.x * 256 + threadIdx.x;
    if (idx < NW) {
        float v = Wih[idx];
        __nv_bfloat16 hi = __float2bfloat16(v);
        g_Wih_h[idx] = hi;
        g_Wih_l[idx] = __float2bfloat16(v - __bfloat162float(hi));
    } else {
        idx -= NW;
        float v = Whh[idx];
        __nv_bfloat16 hi = __float2bfloat16(v);
        g_Whh_h[idx] = hi;
        g_Whh_l[idx] = __float2bfloat16(v - __bfloat162float(hi));
    }
}

// ---------------- HMMA bf16x3 NT GEMM + bias (48KB static smem) ----------------
// C[m][n] = sum_i A[m][i]*W[n][i] + bias[n], via Ah*Bh + Ah*Bl + Al*Bh
// CTA tile 128(M) x 64(N), k-chunk 32, double buffered.
// grid: (NN/64, M/128, Kk) -- n fastest for A-tile L2 reuse
template <int MODE>
__global__ void __launch_bounds__(256, 1) gemm_hmma(const float* __restrict__ biasb) {
    // per-stage layout: A_h[0,8K) A_l[8K,16K) B_h[16K,20K) B_l[20K,24K)
    __shared__ __align__(16) char smem[49152];
    const int A_LO = 8192, B_HI = 16384, B_LO = 20480, STAGE = 24576;

    int tid = threadIdx.x, wid = tid >> 5, lane = tid & 31;
    int z = blockIdx.z;
    int n0 = blockIdx.x * 64, m0 = blockIdx.y * 128;

    const __nv_bfloat16* Ah = (MODE == 0 ? g_xh : g_hh) +
        (size_t)z * (MODE == 0 ? (size_t)Tt * Bb * Hh : (size_t)Bb * Hh);
    const __nv_bfloat16* Al = (MODE == 0 ? g_xl : g_hl) +
        (size_t)z * (MODE == 0 ? (size_t)Tt * Bb * Hh : (size_t)Bb * Hh);
    const __nv_bfloat16* Bh = (MODE == 0 ? g_Wih_h : g_Whh_h) + (size_t)z * NN * Hh;
    const __nv_bfloat16* Bl = (MODE == 0 ? g_Wih_l : g_Whh_l) + (size_t)z * NN * Hh;
    float* C = (MODE == 0 ? g_gi : g_gh) +
        (size_t)z * (MODE == 0 ? (size_t)Tt * Bb * NN : (size_t)Bb * NN);
    const float* bias = biasb + (size_t)z * NN;

    uint32_t sb = smem_u32(smem);
    int warp_m = wid >> 1;     // 4 warps over M (32 rows each)
    int warp_n = wid & 1;      // 2 warps over N (32 cols each)

    float acc[2][4][4];
#pragma unroll
    for (int i = 0; i < 2; i++)
#pragma unroll
        for (int j = 0; j < 4; j++)
#pragma unroll
            for (int q = 0; q < 4; q++) acc[i][j][q] = 0.f;

    // stage loader: A 128x32 (hi+lo), B 64x32 (hi+lo); 1536 16B chunks / 256 thr = 6
    auto load_stage = [&](int s, int k0) {
        uint32_t st = sb + s * STAGE;
#pragma unroll
        for (int i = 0; i < 6; i++) {
            int idx = tid + i * 256;            // 0..1535
            if (idx < 1024) {                   // A hi (0..511) / A lo (512..1023)
                int r = (idx & 511) >> 2;
                int c = idx & 3;
                uint32_t so = st + (idx < 512 ? 0 : A_LO) + swz64(r, c);
                const __nv_bfloat16* g = (idx < 512 ? Ah : Al) + (size_t)(m0 + r) * Hh + k0 + c * 8;
                cp16(so, g);
            } else {                            // B hi (1024..1279) / B lo (1280..1535)
                int li = idx - 1024;
                int r = (li & 255) >> 2;
                int c = li & 3;
                uint32_t so = st + (li < 256 ? B_HI : B_LO) + swz64(r, c);
                const __nv_bfloat16* g = (li < 256 ? Bh : Bl) + (size_t)(n0 + r) * Hh + k0 + c * 8;
                cp16(so, g);
            }
        }
        cp_commit();
    };

    load_stage(0, 0);

    for (int kc = 0; kc < 16; kc++) {
        if (kc < 15) { load_stage((kc + 1) & 1, (kc + 1) * 32); cp_wait<1>(); }
        else cp_wait<0>();
        __syncthreads();

        uint32_t st = sb + (kc & 1) * STAGE;
#pragma unroll
        for (int ks = 0; ks < 2; ks++) {
            uint32_t a_h[2][4], a_l[2][4], b_h[4][2], b_l[4][2];
            int chunk = ks * 2 + (lane >> 4);   // 16B chunk index within 64B row
            // A fragments: 2 m-tiles of 16 rows
#pragma unroll
            for (int mi = 0; mi < 2; mi++) {
                int rr = warp_m * 32 + mi * 16 + (lane & 15);
                uint32_t ad = st + swz64(rr, chunk);
                ldsm_x4(ad, a_h[mi]);
                ldsm_x4(ad + A_LO, a_l[mi]);
            }
            // B fragments: 2 ldmatrix.x4 over 16 n-rows each -> 4 n-tiles of 8
#pragma unroll
            for (int nj = 0; nj < 2; nj++) {
                int rr = warp_n * 32 + nj * 16 + (lane & 15);
                uint32_t bd = st + B_HI + swz64(rr, chunk);
                uint32_t r4[4];
                ldsm_x4(bd, r4);
                b_h[2 * nj][0] = r4[0]; b_h[2 * nj][1] = r4[2];
                b_h[2 * nj + 1][0] = r4[1]; b_h[2 * nj + 1][1] = r4[3];
                ldsm_x4(bd + 4096, r4);   // B_LO = B_HI + 4096
                b_l[2 * nj][0] = r4[0]; b_l[2 * nj][1] = r4[2];
                b_l[2 * nj + 1][0] = r4[1]; b_l[2 * nj + 1][1] = r4[3];
            }
#pragma unroll
            for (int mi = 0; mi < 2; mi++)
#pragma unroll
                for (int ni = 0; ni < 4; ni++) {
                    mma16816(acc[mi][ni], a_h[mi], b_h[ni]);
                    mma16816(acc[mi][ni], a_h[mi], b_l[ni]);
                    mma16816(acc[mi][ni], a_l[mi], b_h[ni]);
                }
        }
        __syncthreads();
    }

    // epilogue: write C + bias
#pragma unroll
    for (int mi = 0; mi < 2; mi++) {
        int row = m0 + warp_m * 32 + mi * 16 + (lane >> 2);
#pragma unroll
        for (int ni = 0; ni < 4; ni++) {
            int col = n0 + warp_n * 32 + ni * 8 + 2 * (lane & 3);
            float2 o0, o1;
            o0.x = acc[mi][ni][0] + bias[col];
            o0.y = acc[mi][ni][1] + bias[col + 1];
            o1.x = acc[mi][ni][2] + bias[col];
            o1.y = acc[mi][ni][3] + bias[col + 1];
            *(float2*)(C + (size_t)row * NN + col) = o0;
            *(float2*)(C + (size_t)(row + 8) * NN + col) = o1;
        }
    }
}

// ---------------- h init (+ split) ----------------
__global__ void init_h_kernel(const float* __restrict__ init) {
    int idx = blockIdx.x * 256 + threadIdx.x;   // K*B*H
    float v = init[idx % (Bb * Hh)];
    g_h[idx] = v;
    __nv_bfloat16 hi = __float2bfloat16(v);
    g_hh[idx] = hi;
    g_hl[idx] = __float2bfloat16(v - __bfloat162float(hi));
}

// ---------------- GRU gate update (per step) + h split ----------------
__global__ void gru_gates(int t) {
    int idx = blockIdx.x * 256 + threadIdx.x;   // over K*B*H
    int k = idx / (Bb * Hh);
    int rem = idx - k * (Bb * Hh);
    int b = rem / Hh;
    int hh = rem - b * Hh;
    const float* gik = g_gi + (((size_t)k * Tt + t) * Bb + b) * NN;
    const float* ghk = g_gh + ((size_t)k * Bb + b) * NN;
    float r = 1.f / (1.f + expf(-(gik[hh] + ghk[hh])));
    float z = 1.f / (1.f + expf(-(gik[Hh + hh] + ghk[Hh + hh])));
    float n = tanhf(gik[2 * Hh + hh] + r * ghk[2 * Hh + hh]);
    float hp = g_h[idx];
    float hnew = (1.f - z) * n + z * hp;
    g_h[idx] = hnew;
    g_hs[(((size_t)k * Tt + t) * Bb + b) * Hh + hh] = hnew;
    __nv_bfloat16 hi = __float2bfloat16(hnew);
    g_hh[idx] = hi;
    g_hl[idx] = __float2bfloat16(hnew - __bfloat162float(hi));
}

// ---------------- output heads ----------------
__global__ void out_kernel(const float* __restrict__ Wout,
                           const float* __restrict__ bout,
                           float* __restrict__ out) {
    int warp = threadIdx.x >> 5;
    int lane = threadIdx.x & 31;
    int oid = blockIdx.x * 8 + warp;
    int pair = oid >> 15;
    int rem = oid & 32767;
    int b = rem >> 6;
    int t = rem & 63;
    const float* hf = g_hs + (((size_t)pair * Tt + t) * Bb + b) * Hh;
    const float* hb = g_hs + (((size_t)(pair + 2) * Tt + (Tt - 1 - t)) * Bb + b) * Hh;
    const float* w = Wout + pair * Hh;
    float s = 0.f;
    for (int i0 = lane * 4; i0 < Hh; i0 += 128) {
        float4 f = *(const float4*)(hf + i0);
        float4 g = *(const float4*)(hb + i0);
        float4 wv = *(const float4*)(w + i0);
        s += (f.x + g.x) * wv.x + (f.y + g.y) * wv.y +
             (f.z + g.z) * wv.z + (f.w + g.w) * wv.w;
    }
#pragma unroll
    for (int o = 16; o; o >>= 1) s += __shfl_xor_sync(0xffffffffu, s, o);
    if (lane == 0) out[(size_t)pair * Bb * Tt + b * Tt + t] = s + bout[pair];
}

// ---------------- launch (kernel launches ONLY; no other host CUDA API) ----------------
extern "C" void kernel_launch(void* const* d_in, const int* in_sizes, int n_in,
                              void* d_out, int out_size) {
    const float* data     = (const float*)d_in[0];
    const float* init     = (const float*)d_in[1];
    const float* fc_in_W  = (const float*)d_in[2];
    const float* fc_in_b  = (const float*)d_in[3];
    const float* Wih      = (const float*)d_in[4];
    const float* Whh      = (const float*)d_in[5];
    const float* bih      = (const float*)d_in[6];
    const float* bhh      = (const float*)d_in[7];
    const float* fc_out_W = (const float*)d_in[8];
    const float* fc_out_b = (const float*)d_in[9];
    float* out = (float*)d_out;

    transpose_data<<<(Tt * Bb * Ff) / 256, 256>>>(data);
    proj_kernel<<<dim3(Bb / 64, Hh / 64, Kk * Tt), 256>>>(fc_in_W, fc_in_b);
    split_w<<<(2 * Kk * NN * Hh) / 256, 256>>>(Wih, Whh);

    // gi = xseq @ Wih^T + bih : M = T*B = 32768
    gemm_hmma<0><<<dim3(NN / 64, (Tt * Bb) / 128, Kk), 256>>>(bih);

    init_h_kernel<<<(Kk * Bb * Hh) / 256, 256>>>(init);

    for (int t = 0; t < Tt; t++) {
        // gh = h @ Whh^T + bhh : M = B = 512
        gemm_hmma<1><<<dim3(NN / 64, Bb / 128, Kk), 256>>>(bhh);
        gru_gates<<<(Kk * Bb * Hh) / 256, 256>>>(t);
    }

    out_kernel<<<(2 * Bb * Tt) / 8, 256>>>(fc_out_W, fc_out_b, out);
}